// round 17
// baseline (speedup 1.0000x reference)
#include <cuda_runtime.h>
#include <math.h>
#include <stdint.h>

// Problem constants
#define BN   1024   // batch
#define MU   8      // memory units
#define RN   512    // neurons per unit
#define IN_  512    // input dim
#define ON   512    // output dim
#define AN   16     // attention dim
#define DN   128    // M*A
#define NSQ  10     // number of matrix squarings for spectral radius
#define KC   16     // K-chunk for tiled GEMMs

// -------- scratch (device globals; no allocation allowed) --------
__device__ float g_P[2][MU * RN * RN];          // ping-pong squaring buffers (16 MB)
__device__ float g_Yp[4][BN * ON];              // split-K partials for Yi (8 MB)
__device__ float g_nrm2[NSQ + 2][MU];           // Frobenius norm^2 per step per unit
__device__ float g_sc[MU];                      // sr[m] / rho[m]
__device__ float g_Qa[BN * MU * AN];            // attention Q  [b][q][a]
__device__ float g_KV[BN * MU * 256];           // [b*8+n][ K(m,a) | V(m,a) ]
__device__ float g_Ui[BN * MU * DN];            // Ui [b][m][d]

// -------- packed f32x2 helpers --------
__device__ __forceinline__ void ffma2(uint64_t& d, uint64_t a, uint64_t b) {
    asm("fma.rn.f32x2 %0, %1, %2, %0;" : "+l"(d) : "l"(a), "l"(b));
}
__device__ __forceinline__ void unpack2(uint64_t v, float& lo, float& hi) {
    asm("mov.b64 {%0, %1}, %2;" : "=f"(lo), "=f"(hi) : "l"(v));
}

// -------- helpers --------
__device__ __forceinline__ float blockReduceSum(float v) {
    __shared__ float red[16];
    #pragma unroll
    for (int o = 16; o > 0; o >>= 1) v += __shfl_down_sync(0xffffffffu, v, o);
    int w = threadIdx.x >> 5, l = threadIdx.x & 31;
    if (l == 0) red[w] = v;
    __syncthreads();
    float r = 0.f;
    if (w == 0) {
        int nw = blockDim.x >> 5;
        r = (l < nw) ? red[l] : 0.f;
        #pragma unroll
        for (int o = 8; o > 0; o >>= 1) r += __shfl_down_sync(0xffffffffu, r, o);
    }
    return r;   // valid on thread 0
}

// -------- init: zero the norm accumulators --------
__global__ void k_init() {
    int t = threadIdx.x;
    if (t < (NSQ + 2) * MU) ((float*)g_nrm2)[t] = 0.f;
}

// -------- ||W_m||_F^2  (nrm2[0]) --------
__global__ void k_norm0(const float* __restrict__ W) {
    int m = blockIdx.y;
    const float* p = W + m * RN * RN;
    float s = 0.f;
    for (int i = blockIdx.x * blockDim.x + threadIdx.x; i < RN * RN;
         i += gridDim.x * blockDim.x) {
        float v = p[i];
        s += v * v;
    }
    float tot = blockReduceSum(s);
    if (threadIdx.x == 0) atomicAdd(&g_nrm2[0][m], tot);
}

// ==================================================================
// Squaring step: N_{j+1} = N_j^2 / nrm2[j]; accumulates nrm2[j+1].
// 128x128 tile, 512 threads, 4x8 acc, dup-A smem (no pack movs),
// double-buffered. grid (4,4,8) = 128 CTAs, single wave.
// ==================================================================
__global__ void __launch_bounds__(512, 1) k_sqr(const float* __restrict__ W, int j) {
    int m = blockIdx.z;
    const float* src = (j == 0) ? (W + m * RN * RN) : (g_P[(j - 1) & 1] + m * RN * RN);
    float* dst = g_P[j & 1] + m * RN * RN;
    float inv = 1.0f / g_nrm2[j][m];

    __shared__ float As[2][KC][256];   // dup pairs: As[.][k][2r]=As[.][k][2r+1]=A[r][k]
    __shared__ float Bs[2][KC][128];

    int t  = threadIdx.x;             // 0..511
    int tx = t & 15, ty = t >> 4;     // 16 col-groups x 32 row-groups (4 rows each)
    int rowBase = blockIdx.y * 128;
    int colBase = blockIdx.x * 128;

    int arow = t & 127;               // A loader: row, 4 consecutive k
    int kq   = (t >> 7) * 4;          // 0,4,8,12
    int bk   = t >> 5;                // B loader: k row 0..15
    int bc4  = (t & 31) * 4;          // 4 cols

    uint64_t acc[4][4];
    #pragma unroll
    for (int i = 0; i < 4; i++)
        #pragma unroll
        for (int jp = 0; jp < 4; jp++) acc[i][jp] = 0ull;

    float4 pa, pb;
    pa = *(const float4*)(src + (rowBase + arow) * RN + kq);
    pb = *(const float4*)(src + bk * RN + colBase + bc4);
    {
        float va[4] = {pa.x, pa.y, pa.z, pa.w};
        #pragma unroll
        for (int i = 0; i < 4; i++)
            *(float2*)&As[0][kq + i][2 * arow] = make_float2(va[i], va[i]);
        *(float4*)&Bs[0][bk][bc4] = pb;
    }
    __syncthreads();

    const int NCH = RN / KC;   // 32
    for (int c = 0; c < NCH; c++) {
        int buf = c & 1, nxt = buf ^ 1;
        if (c + 1 < NCH) {
            int kn = (c + 1) * KC;
            pa = *(const float4*)(src + (rowBase + arow) * RN + kn + kq);
            pb = *(const float4*)(src + (kn + bk) * RN + colBase + bc4);
        }

        #pragma unroll
        for (int k = 0; k < KC; k++) {
            ulonglong2 a01 = *(const ulonglong2*)&As[buf][k][ty * 8];
            ulonglong2 a23 = *(const ulonglong2*)&As[buf][k][ty * 8 + 4];
            ulonglong2 b01 = *(const ulonglong2*)&Bs[buf][k][tx * 8];
            ulonglong2 b23 = *(const ulonglong2*)&Bs[buf][k][tx * 8 + 4];
            uint64_t ad[4] = {a01.x, a01.y, a23.x, a23.y};
            uint64_t bp[4] = {b01.x, b01.y, b23.x, b23.y};
            #pragma unroll
            for (int i = 0; i < 4; i++)
                #pragma unroll
                for (int jp = 0; jp < 4; jp++) ffma2(acc[i][jp], ad[i], bp[jp]);
        }

        if (c + 1 < NCH) {
            float va[4] = {pa.x, pa.y, pa.z, pa.w};
            #pragma unroll
            for (int i = 0; i < 4; i++)
                *(float2*)&As[nxt][kq + i][2 * arow] = make_float2(va[i], va[i]);
            *(float4*)&Bs[nxt][bk][bc4] = pb;
        }
        __syncthreads();
    }

    float ss = 0.f;
    #pragma unroll
    for (int i = 0; i < 4; i++) {
        int gr = rowBase + ty * 4 + i;
        float cv[8];
        #pragma unroll
        for (int jp = 0; jp < 4; jp++) {
            unpack2(acc[i][jp], cv[2 * jp], cv[2 * jp + 1]);
            cv[2 * jp] *= inv; cv[2 * jp + 1] *= inv;
        }
        float4 o0 = make_float4(cv[0], cv[1], cv[2], cv[3]);
        float4 o1 = make_float4(cv[4], cv[5], cv[6], cv[7]);
        *(float4*)(dst + gr * RN + colBase + tx * 8)     = o0;
        *(float4*)(dst + gr * RN + colBase + tx * 8 + 4) = o1;
        ss += o0.x * o0.x + o0.y * o0.y + o0.z * o0.z + o0.w * o0.w;
        ss += o1.x * o1.x + o1.y * o1.y + o1.z * o1.z + o1.w * o1.w;
    }
    float tot = blockReduceSum(ss);
    if (threadIdx.x == 0) atomicAdd(&g_nrm2[j + 1][m], tot);
}

// -------- finalize: rho and scale = sr/rho --------
__global__ void k_finalize(const float* __restrict__ sr) {
    int m = threadIdx.x;
    if (m < MU) {
        double acc = 0.0, w = 1.0;
        for (int j = 0; j <= NSQ; j++) {
            acc += w * 0.5 * log((double)g_nrm2[j][m]);
            w *= 0.5;
        }
        float rho = (float)exp(acc);
        g_sc[m] = sr[m] / rho;
    }
}

// -------- Q = Xi @ Wq  -> g_Qa [1024 x 128] --------
__global__ void __launch_bounds__(256) k_gemmQ(const float* __restrict__ Xi,
                                               const float* __restrict__ Wq) {
    __shared__ float As[16][64];
    __shared__ float Bs[16][64];
    int t = threadIdx.x;
    int tx = t & 15, ty = t >> 4;
    int ar = t >> 2, ak = (t & 3) * 4;
    int bk = t >> 4, bc = (t & 15) * 4;
    int rb = blockIdx.y * 64, cb = blockIdx.x * 64;

    float acc[4][4];
    #pragma unroll
    for (int i = 0; i < 4; i++)
        #pragma unroll
        for (int jj = 0; jj < 4; jj++) acc[i][jj] = 0.f;

    for (int kt = 0; kt < IN_; kt += 16) {
        float4 av = *(const float4*)(Xi + (rb + ar) * IN_ + kt + ak);
        int c0 = cb + bc;
        float4 bv = *(const float4*)(Wq + (c0 >> 4) * (IN_ * AN) + (kt + bk) * AN + (c0 & 15));
        As[ak + 0][ar] = av.x; As[ak + 1][ar] = av.y;
        As[ak + 2][ar] = av.z; As[ak + 3][ar] = av.w;
        *(float4*)&Bs[bk][bc] = bv;
        __syncthreads();
        #pragma unroll
        for (int k = 0; k < 16; k++) {
            float4 a = *(const float4*)&As[k][ty * 4];
            float4 b = *(const float4*)&Bs[k][tx * 4];
            float arr[4] = {a.x, a.y, a.z, a.w};
            float brr[4] = {b.x, b.y, b.z, b.w};
            #pragma unroll
            for (int i = 0; i < 4; i++)
                #pragma unroll
                for (int jj = 0; jj < 4; jj++) acc[i][jj] += arr[i] * brr[jj];
        }
        __syncthreads();
    }
    #pragma unroll
    for (int i = 0; i < 4; i++)
        #pragma unroll
        for (int jj = 0; jj < 4; jj++)
            g_Qa[(rb + ty * 4 + i) * DN + cb + tx * 4 + jj] = acc[i][jj];
}

// -------- K|V = Si @ [Wk|Wv] -> g_KV [8192 x 256] --------
__global__ void __launch_bounds__(256) k_gemmKV(const float* __restrict__ Si,
                                                const float* __restrict__ Wk,
                                                const float* __restrict__ Wv) {
    __shared__ float As[16][64];
    __shared__ float Bs[16][64];
    int t = threadIdx.x;
    int tx = t & 15, ty = t >> 4;
    int ar = t >> 2, ak = (t & 3) * 4;
    int bk = t >> 4, bc = (t & 15) * 4;
    int rb = blockIdx.y * 64, cb = blockIdx.x * 64;

    float acc[4][4];
    #pragma unroll
    for (int i = 0; i < 4; i++)
        #pragma unroll
        for (int jj = 0; jj < 4; jj++) acc[i][jj] = 0.f;

    for (int kt = 0; kt < RN; kt += 16) {
        float4 av = *(const float4*)(Si + (rb + ar) * RN + kt + ak);
        int c0 = cb + bc;
        const float* base = (c0 < 128) ? Wk : Wv;
        int cl = c0 & 127;
        float4 bv = *(const float4*)(base + (cl >> 4) * (RN * AN) + (kt + bk) * AN + (cl & 15));
        As[ak + 0][ar] = av.x; As[ak + 1][ar] = av.y;
        As[ak + 2][ar] = av.z; As[ak + 3][ar] = av.w;
        *(float4*)&Bs[bk][bc] = bv;
        __syncthreads();
        #pragma unroll
        for (int k = 0; k < 16; k++) {
            float4 a = *(const float4*)&As[k][ty * 4];
            float4 b = *(const float4*)&Bs[k][tx * 4];
            float arr[4] = {a.x, a.y, a.z, a.w};
            float brr[4] = {b.x, b.y, b.z, b.w};
            #pragma unroll
            for (int i = 0; i < 4; i++)
                #pragma unroll
                for (int jj = 0; jj < 4; jj++) acc[i][jj] += arr[i] * brr[jj];
        }
        __syncthreads();
    }
    #pragma unroll
    for (int i = 0; i < 4; i++)
        #pragma unroll
        for (int jj = 0; jj < 4; jj++)
            g_KV[(rb + ty * 4 + i) * 256 + cb + tx * 4 + jj] = acc[i][jj];
}

// -------- attention: scores -> softmax -> /sqrt(D) -> Ui --------
__global__ void k_attn() {
    int idx = blockIdx.x * blockDim.x + threadIdx.x;
    if (idx >= BN * MU * MU) return;
    int b = idx >> 6;
    int m = (idx >> 3) & 7;
    int q = idx & 7;

    float qv[AN];
    const float* Qp = g_Qa + b * DN + q * AN;
    #pragma unroll
    for (int a = 0; a < AN; a++) qv[a] = Qp[a];

    float s[MU];
    #pragma unroll
    for (int n = 0; n < MU; n++) {
        const float* Kp = g_KV + (b * MU + n) * 256 + m * AN;
        float d = 0.f;
        #pragma unroll
        for (int a = 0; a < AN; a++) d += qv[a] * Kp[a];
        s[n] = d;
    }
    float mx = s[0];
    #pragma unroll
    for (int n = 1; n < MU; n++) mx = fmaxf(mx, s[n]);
    float sum = 0.f;
    #pragma unroll
    for (int n = 0; n < MU; n++) { s[n] = __expf(s[n] - mx); sum += s[n]; }
    float scale = 1.0f / (sum * sqrtf((float)DN));
    #pragma unroll
    for (int n = 0; n < MU; n++) s[n] *= scale;

    float* Up = g_Ui + (b * MU + m) * DN + q * AN;
    #pragma unroll
    for (int a = 0; a < AN; a++) {
        float u = 0.f;
        #pragma unroll
        for (int n = 0; n < MU; n++)
            u += s[n] * g_KV[(b * MU + n) * 256 + 128 + m * AN + a];
        Up[a] = u;
    }
}

// -------- state update: Snew = (1-lr)Si + lr*tanh(Ui@Win + Si@(W*sc) + bias) --------
// concat-K GEMM, dup-A no-pack inner, double-buffered. grid (4,8,8), 256 thr.
__global__ void __launch_bounds__(256, 2) k_state(const float* __restrict__ Si,
                                                  const float* __restrict__ Win,
                                                  const float* __restrict__ W,
                                                  const float* __restrict__ bias,
                                                  const float* __restrict__ lr,
                                                  float* __restrict__ Snew) {
    int m = blockIdx.z;
    float scm = g_sc[m];
    float lrm = lr[m];

    __shared__ float As[2][KC][256];   // dup pairs
    __shared__ float Bs[2][KC][128];

    int t  = threadIdx.x;
    int tx = t & 15, ty = t >> 4;      // 16 x 16 (8 rows, 8 cols each)
    int rowBase = blockIdx.y * 128;
    int colBase = blockIdx.x * 128;

    int ar = t & 127;
    int aq = (t >> 7) * 8;             // 0 or 8: this thread loads 8 k for its row

    uint64_t acc[8][4];
    #pragma unroll
    for (int i = 0; i < 8; i++)
        #pragma unroll
        for (int jp = 0; jp < 4; jp++) acc[i][jp] = 0ull;

    float4 pa[2], pb[2];
    #pragma unroll
    for (int q = 0; q < 2; q++)
        pa[q] = *(const float4*)(g_Ui + ((rowBase + ar) * MU + m) * DN + aq + q * 4);
    #pragma unroll
    for (int q = 0; q < 2; q++) {
        int f = t + q * 256;
        pb[q] = *(const float4*)(Win + m * (DN * RN) + (f >> 5) * RN + colBase + (f & 31) * 4);
    }
    #pragma unroll
    for (int q = 0; q < 2; q++) {
        float va[4] = {pa[q].x, pa[q].y, pa[q].z, pa[q].w};
        #pragma unroll
        for (int i = 0; i < 4; i++)
            *(float2*)&As[0][aq + q * 4 + i][2 * ar] = make_float2(va[i], va[i]);
        int f = t + q * 256;
        *(float4*)&Bs[0][f >> 5][(f & 31) * 4] = pb[q];
    }
    __syncthreads();

    const int NCH = (DN + RN) / KC;   // 40
    for (int c = 0; c < NCH; c++) {
        int buf = c & 1, nxt = buf ^ 1;
        if (c + 1 < NCH) {
            int kn = (c + 1) * KC;
            #pragma unroll
            for (int q = 0; q < 2; q++) {
                int kA = kn + aq + q * 4;
                int brow = rowBase + ar;
                if (kA < DN)
                    pa[q] = *(const float4*)(g_Ui + (brow * MU + m) * DN + kA);
                else
                    pa[q] = *(const float4*)(Si + brow * (MU * RN) + m * RN + (kA - DN));
            }
            #pragma unroll
            for (int q = 0; q < 2; q++) {
                int f = t + q * 256;
                int kB = kn + (f >> 5);
                int c4 = (f & 31) * 4;
                if (kB < DN) {
                    pb[q] = *(const float4*)(Win + m * (DN * RN) + kB * RN + colBase + c4);
                } else {
                    pb[q] = *(const float4*)(W + m * (RN * RN) + (kB - DN) * RN + colBase + c4);
                    pb[q].x *= scm; pb[q].y *= scm; pb[q].z *= scm; pb[q].w *= scm;
                }
            }
        }

        #pragma unroll
        for (int k = 0; k < KC; k++) {
            ulonglong2 a01 = *(const ulonglong2*)&As[buf][k][ty * 16];
            ulonglong2 a23 = *(const ulonglong2*)&As[buf][k][ty * 16 + 4];
            ulonglong2 a45 = *(const ulonglong2*)&As[buf][k][ty * 16 + 8];
            ulonglong2 a67 = *(const ulonglong2*)&As[buf][k][ty * 16 + 12];
            ulonglong2 b01 = *(const ulonglong2*)&Bs[buf][k][tx * 8];
            ulonglong2 b23 = *(const ulonglong2*)&Bs[buf][k][tx * 8 + 4];
            uint64_t ad[8] = {a01.x, a01.y, a23.x, a23.y, a45.x, a45.y, a67.x, a67.y};
            uint64_t bp[4] = {b01.x, b01.y, b23.x, b23.y};
            #pragma unroll
            for (int i = 0; i < 8; i++)
                #pragma unroll
                for (int jp = 0; jp < 4; jp++) ffma2(acc[i][jp], ad[i], bp[jp]);
        }

        if (c + 1 < NCH) {
            #pragma unroll
            for (int q = 0; q < 2; q++) {
                float va[4] = {pa[q].x, pa[q].y, pa[q].z, pa[q].w};
                #pragma unroll
                for (int i = 0; i < 4; i++)
                    *(float2*)&As[nxt][aq + q * 4 + i][2 * ar] = make_float2(va[i], va[i]);
                int f = t + q * 256;
                *(float4*)&Bs[nxt][f >> 5][(f & 31) * 4] = pb[q];
            }
        }
        __syncthreads();
    }

    #pragma unroll
    for (int i = 0; i < 8; i++) {
        int b = rowBase + ty * 8 + i;
        #pragma unroll
        for (int jp = 0; jp < 4; jp++) {
            float lo, hi;
            unpack2(acc[i][jp], lo, hi);
            int r0 = colBase + tx * 8 + 2 * jp;
            float x0 = lo + bias[m * RN + r0];
            float x1 = hi + bias[m * RN + r0 + 1];
            float s0 = Si[b * (MU * RN) + m * RN + r0];
            float s1 = Si[b * (MU * RN) + m * RN + r0 + 1];
            Snew[b * (MU * RN) + m * RN + r0]     = (1.0f - lrm) * s0 + lrm * tanhf(x0);
            Snew[b * (MU * RN) + m * RN + r0 + 1] = (1.0f - lrm) * s1 + lrm * tanhf(x1);
        }
    }
}

// -------- Yi partials: g_Yp[z] = Snew[:, z*1024:...] @ Wout[z*1024:...] --------
// 128x128 tile, 512 thr, dup-A no-pack, double-buffered. grid (4,8,4) = 128 CTAs.
__global__ void __launch_bounds__(512, 1) k_gemmYi_p(const float* __restrict__ Snew,
                                                     const float* __restrict__ Wout) {
    const int K = MU * RN;            // 4096
    const int KSEG = K / 4;           // 1024
    int z = blockIdx.z;
    int k0 = z * KSEG;
    float* dst = g_Yp[z];

    __shared__ float As[2][KC][256];
    __shared__ float Bs[2][KC][128];

    int t  = threadIdx.x;
    int tx = t & 15, ty = t >> 4;     // 16 x 32 (4 rows each)
    int rowBase = blockIdx.y * 128;
    int colBase = blockIdx.x * 128;

    int arow = t & 127;
    int kq   = (t >> 7) * 4;
    int bk   = t >> 5;
    int bc4  = (t & 31) * 4;

    uint64_t acc[4][4];
    #pragma unroll
    for (int i = 0; i < 4; i++)
        #pragma unroll
        for (int jp = 0; jp < 4; jp++) acc[i][jp] = 0ull;

    float4 pa, pb;
    pa = *(const float4*)(Snew + (rowBase + arow) * K + k0 + kq);
    pb = *(const float4*)(Wout + (k0 + bk) * ON + colBase + bc4);
    {
        float va[4] = {pa.x, pa.y, pa.z, pa.w};
        #pragma unroll
        for (int i = 0; i < 4; i++)
            *(float2*)&As[0][kq + i][2 * arow] = make_float2(va[i], va[i]);
        *(float4*)&Bs[0][bk][bc4] = pb;
    }
    __syncthreads();

    const int NCH = KSEG / KC;   // 64
    for (int c = 0; c < NCH; c++) {
        int buf = c & 1, nxt = buf ^ 1;
        if (c + 1 < NCH) {
            int kn = k0 + (c + 1) * KC;
            pa = *(const float4*)(Snew + (rowBase + arow) * K + kn + kq);
            pb = *(const float4*)(Wout + (kn + bk) * ON + colBase + bc4);
        }

        #pragma unroll
        for (int k = 0; k < KC; k++) {
            ulonglong2 a01 = *(const ulonglong2*)&As[buf][k][ty * 8];
            ulonglong2 a23 = *(const ulonglong2*)&As[buf][k][ty * 8 + 4];
            ulonglong2 b01 = *(const ulonglong2*)&Bs[buf][k][tx * 8];
            ulonglong2 b23 = *(const ulonglong2*)&Bs[buf][k][tx * 8 + 4];
            uint64_t ad[4] = {a01.x, a01.y, a23.x, a23.y};
            uint64_t bp[4] = {b01.x, b01.y, b23.x, b23.y};
            #pragma unroll
            for (int i = 0; i < 4; i++)
                #pragma unroll
                for (int jp = 0; jp < 4; jp++) ffma2(acc[i][jp], ad[i], bp[jp]);
        }

        if (c + 1 < NCH) {
            float va[4] = {pa.x, pa.y, pa.z, pa.w};
            #pragma unroll
            for (int i = 0; i < 4; i++)
                *(float2*)&As[nxt][kq + i][2 * arow] = make_float2(va[i], va[i]);
            *(float4*)&Bs[nxt][bk][bc4] = pb;
        }
        __syncthreads();
    }

    #pragma unroll
    for (int i = 0; i < 4; i++) {
        int gr = rowBase + ty * 4 + i;
        float cv[8];
        #pragma unroll
        for (int jp = 0; jp < 4; jp++)
            unpack2(acc[i][jp], cv[2 * jp], cv[2 * jp + 1]);
        *(float4*)(dst + gr * ON + colBase + tx * 8)     = make_float4(cv[0], cv[1], cv[2], cv[3]);
        *(float4*)(dst + gr * ON + colBase + tx * 8 + 4) = make_float4(cv[4], cv[5], cv[6], cv[7]);
    }
}

// -------- Yi = sum of 4 split-K partials (deterministic fixed order) --------
__global__ void k_yred(float* __restrict__ Yi) {
    int i = (blockIdx.x * blockDim.x + threadIdx.x) * 4;
    float4 a = *(const float4*)(g_Yp[0] + i);
    float4 b = *(const float4*)(g_Yp[1] + i);
    float4 c = *(const float4*)(g_Yp[2] + i);
    float4 d = *(const float4*)(g_Yp[3] + i);
    float4 o;
    o.x = (a.x + b.x) + (c.x + d.x);
    o.y = (a.y + b.y) + (c.y + d.y);
    o.z = (a.z + b.z) + (c.z + d.z);
    o.w = (a.w + b.w) + (c.w + d.w);
    *(float4*)(Yi + i) = o;
}

// ------------------------------------------------------------------
extern "C" void kernel_launch(void* const* d_in, const int* in_sizes, int n_in,
                              void* d_out, int out_size) {
    const float* Xi   = (const float*)d_in[0];
    const float* Si   = (const float*)d_in[1];
    const float* Wq   = (const float*)d_in[2];
    const float* Wk   = (const float*)d_in[3];
    const float* Wv   = (const float*)d_in[4];
    const float* Wout = (const float*)d_in[5];
    const float* W    = (const float*)d_in[6];
    const float* Win  = (const float*)d_in[7];
    const float* bias = (const float*)d_in[8];
    const float* sr   = (const float*)d_in[9];
    const float* lr   = (const float*)d_in[10];

    float* Yi   = (float*)d_out;
    float* Snew = (float*)d_out + BN * ON;

    // --- spectral radius via normalized repeated squaring ---
    k_init<<<1, 256>>>();
    k_norm0<<<dim3(16, 8), 256>>>(W);
    for (int j = 0; j < NSQ; j++)
        k_sqr<<<dim3(4, 4, 8), 512>>>(W, j);
    k_finalize<<<1, 32>>>(sr);

    // --- attention path ---
    k_gemmQ<<<dim3(2, 16), 256>>>(Xi, Wq);
    k_gemmKV<<<dim3(4, 128), 256>>>(Si, Wk, Wv);
    k_attn<<<BN * MU * MU / 256, 256>>>();

    // --- reservoir state update (fused feed+echo+tanh+leak) ---
    k_state<<<dim3(4, 8, 8), 256>>>(Si, Win, W, bias, lr, Snew);

    // --- readout: split-K partials + deterministic reduce ---
    k_gemmYi_p<<<dim3(4, 8, 4), 512>>>(Snew, Wout);
    k_yred<<<BN * ON / 1024, 256>>>(Yi);
}